// round 8
// baseline (speedup 1.0000x reference)
#include <cuda_runtime.h>
#include <math.h>

#define N_NODES  50000
#define N_EDGES  800000
#define N_GRAPHS 256
#define FEAT     128
#define STATE    64
#define ROUNDS   4
#define M_OUT    32

// Scratch (allocation-free rule: __device__ globals)
__device__ float g_state[N_NODES * STATE];   // 12.8 MB
__device__ float g_msg[N_NODES * STATE];     // 12.8 MB
__device__ float g_agg[N_NODES * STATE];     // 12.8 MB
__device__ float g_graph[N_GRAPHS * STATE];  // 64 KB

// ---------------------------------------------------------------------------
// Zero agg + graph accumulators (agg only needed once: upd kernel re-zeroes)
// ---------------------------------------------------------------------------
__global__ void k_zero() {
    int t = blockIdx.x * blockDim.x + threadIdx.x;
    if (t < N_NODES * STATE) g_agg[t] = 0.0f;
    if (t < N_GRAPHS * STATE) g_graph[t] = 0.0f;
}

// ---------------------------------------------------------------------------
// state = relu(x @ in_W + in_b)   [50000,128] @ [128,64]
// block = 256 threads = 4 rows x 64 cols; W staged in smem (32 KB)
// ---------------------------------------------------------------------------
__global__ void k_input(const float* __restrict__ x,
                        const float* __restrict__ W,
                        const float* __restrict__ b) {
    __shared__ float sW[FEAT * STATE];
    __shared__ float sx[4][FEAT];
    for (int i = threadIdx.x; i < FEAT * STATE; i += 256) sW[i] = W[i];

    int sub = threadIdx.x >> 6;        // 0..3  (row within block)
    int col = threadIdx.x & 63;        // 0..63 (output column)
    int row = blockIdx.x * 4 + sub;

    if (row < N_NODES) {
        sx[sub][col]      = x[row * FEAT + col];
        sx[sub][col + 64] = x[row * FEAT + col + 64];
    }
    __syncthreads();

    if (row >= N_NODES) return;
    float acc = b[col];
#pragma unroll 16
    for (int k = 0; k < FEAT; k++)
        acc = fmaf(sx[sub][k], sW[k * STATE + col], acc);
    g_state[row * STATE + col] = fmaxf(acc, 0.0f);
}

// ---------------------------------------------------------------------------
// message = relu(state @ msg_W[r] + msg_b[r])   [50000,64] @ [64,64]
// ---------------------------------------------------------------------------
__global__ void k_msg(const float* __restrict__ W, const float* __restrict__ b) {
    __shared__ float sW[STATE * STATE];
    __shared__ float sx[4][STATE];
    for (int i = threadIdx.x; i < STATE * STATE; i += 256) sW[i] = W[i];

    int sub = threadIdx.x >> 6;
    int col = threadIdx.x & 63;
    int row = blockIdx.x * 4 + sub;

    if (row < N_NODES) sx[sub][col] = g_state[row * STATE + col];
    __syncthreads();

    if (row >= N_NODES) return;
    float acc = b[col];
#pragma unroll 16
    for (int k = 0; k < STATE; k++)
        acc = fmaf(sx[sub][k], sW[k * STATE + col], acc);
    g_msg[row * STATE + col] = fmaxf(acc, 0.0f);
}

// ---------------------------------------------------------------------------
// Edge gather + scatter-add:  agg[dst] += message[src]
// Indices are INT32 on the wire (JAX x64 disabled downcasts int64->int32).
// 16 threads per edge, float4 chunks, vectorized red.global.add.v4.f32.
// message & agg are L2-resident (12.8 MB each) -> L2 bandwidth bound.
// ---------------------------------------------------------------------------
__global__ void k_edge(const int* __restrict__ ei) {
    int t = blockIdx.x * blockDim.x + threadIdx.x;
    int e = t >> 4;
    if (e >= N_EDGES) return;
    int c = (t & 15) << 2;                       // float offset within row
    int s = __ldg(&ei[e]);                       // src (row 0 of edge_index)
    int d = __ldg(&ei[N_EDGES + e]);             // dst (row 1)

    const float4 v = *reinterpret_cast<const float4*>(&g_msg[s * STATE + c]);
    float* a = &g_agg[d * STATE + c];
    asm volatile("red.global.add.v4.f32 [%0], {%1,%2,%3,%4};"
                 :: "l"(a), "f"(v.x), "f"(v.y), "f"(v.z), "f"(v.w)
                 : "memory");
}

// ---------------------------------------------------------------------------
// state = state + relu(agg @ upd_W[r] + upd_b[r]); then agg row := 0
// ---------------------------------------------------------------------------
__global__ void k_upd(const float* __restrict__ W, const float* __restrict__ b) {
    __shared__ float sW[STATE * STATE];
    __shared__ float sa[4][STATE];
    for (int i = threadIdx.x; i < STATE * STATE; i += 256) sW[i] = W[i];

    int sub = threadIdx.x >> 6;
    int col = threadIdx.x & 63;
    int row = blockIdx.x * 4 + sub;

    if (row < N_NODES) sa[sub][col] = g_agg[row * STATE + col];
    __syncthreads();

    if (row >= N_NODES) return;
    float acc = b[col];
#pragma unroll 16
    for (int k = 0; k < STATE; k++)
        acc = fmaf(sa[sub][k], sW[k * STATE + col], acc);
    int idx = row * STATE + col;
    g_state[idx] = g_state[idx] + fmaxf(acc, 0.0f);
    g_agg[idx] = 0.0f;                 // re-zero for next round (fused)
}

// ---------------------------------------------------------------------------
// graph_state = segment_sum(state, batch)  -> [256, 64]   (batch is int32)
// ---------------------------------------------------------------------------
__global__ void k_pool(const int* __restrict__ batch) {
    int t = blockIdx.x * blockDim.x + threadIdx.x;
    int row = t >> 4;
    if (row >= N_NODES) return;
    int c = (t & 15) << 2;
    int g = __ldg(&batch[row]);

    const float4 v = *reinterpret_cast<const float4*>(&g_state[row * STATE + c]);
    float* a = &g_graph[g * STATE + c];
    asm volatile("red.global.add.v4.f32 [%0], {%1,%2,%3,%4};"
                 :: "l"(a), "f"(v.x), "f"(v.y), "f"(v.z), "f"(v.w)
                 : "memory");
}

// ---------------------------------------------------------------------------
// mean = gs @ mean_W + mean_b ; std = exp(0.5*clip(gs @ lv_W + lv_b, -20, 2))
// out layout [2, 256, 32]
// ---------------------------------------------------------------------------
__global__ void k_head(const float* __restrict__ meanW, const float* __restrict__ meanB,
                       const float* __restrict__ lvW,   const float* __restrict__ lvB,
                       float* __restrict__ out) {
    __shared__ float s[STATE];
    int g = blockIdx.x;
    int m = threadIdx.x;                 // 0..31
    s[m]      = g_graph[g * STATE + m];
    s[m + 32] = g_graph[g * STATE + m + 32];
    __syncthreads();

    float accM = meanB[m];
    float accL = lvB[m];
#pragma unroll
    for (int k = 0; k < STATE; k++) {
        float sv = s[k];
        accM = fmaf(sv, meanW[k * M_OUT + m], accM);
        accL = fmaf(sv, lvW[k * M_OUT + m], accL);
    }
    out[g * M_OUT + m] = accM;
    float lv = fminf(fmaxf(accL, -20.0f), 2.0f);
    out[N_GRAPHS * M_OUT + g * M_OUT + m] = expf(0.5f * lv);
}

// ---------------------------------------------------------------------------
extern "C" void kernel_launch(void* const* d_in, const int* in_sizes, int n_in,
                              void* d_out, int out_size) {
    const float* x     = (const float*)d_in[0];
    const int*   ei    = (const int*)d_in[1];      // int32 (JAX x64 off)
    const int*   batch = (const int*)d_in[2];      // int32
    const float* in_W  = (const float*)d_in[3];
    const float* in_b  = (const float*)d_in[4];
    const float* msg_W = (const float*)d_in[5];    // [4,64,64]
    const float* msg_b = (const float*)d_in[6];    // [4,64]
    const float* upd_W = (const float*)d_in[7];
    const float* upd_b = (const float*)d_in[8];
    const float* meanW = (const float*)d_in[9];
    const float* meanB = (const float*)d_in[10];
    const float* lvW   = (const float*)d_in[11];
    const float* lvB   = (const float*)d_in[12];
    float* out = (float*)d_out;

    const int rowBlocks  = (N_NODES + 3) / 4;                       // 12500
    const int zeroBlocks = (N_NODES * STATE + 255) / 256;           // 12500
    const int edgeBlocks = (N_EDGES * 16 + 255) / 256;              // 50000
    const int poolBlocks = (N_NODES * 16 + 255) / 256;              // 3125

    k_zero<<<zeroBlocks, 256>>>();
    k_input<<<rowBlocks, 256>>>(x, in_W, in_b);

    for (int r = 0; r < ROUNDS; r++) {
        k_msg<<<rowBlocks, 256>>>(msg_W + r * STATE * STATE, msg_b + r * STATE);
        k_edge<<<edgeBlocks, 256>>>(ei);
        k_upd<<<rowBlocks, 256>>>(upd_W + r * STATE * STATE, upd_b + r * STATE);
    }

    k_pool<<<poolBlocks, 256>>>(batch);
    k_head<<<N_GRAPHS, M_OUT>>>(meanW, meanB, lvW, lvB, out);
}

// round 9
// speedup vs baseline: 2.2407x; 2.2407x over previous
#include <cuda_runtime.h>
#include <math.h>

#define N_NODES  50000
#define N_EDGES  800000
#define N_GRAPHS 256
#define FEAT     128
#define STATE    64
#define ROUNDS   4
#define M_OUT    32

#define TILE_ROWS 64
#define APITCH    68          // padded smem pitch (floats) -> no bank conflicts
#define ROW_BLOCKS ((N_NODES + TILE_ROWS - 1) / TILE_ROWS)   // 782

// Scratch (allocation-free rule: __device__ globals)
__device__ float g_state[N_NODES * STATE];   // 12.8 MB
__device__ float g_msg[N_NODES * STATE];     // 12.8 MB
__device__ float g_agg[N_NODES * STATE];     // 12.8 MB
__device__ float g_graph[N_GRAPHS * STATE];  // 64 KB

// ---------------------------------------------------------------------------
// Zero agg + graph accumulators (k_upd re-zeroes agg each round thereafter)
// ---------------------------------------------------------------------------
__global__ void k_zero() {
    int t = blockIdx.x * blockDim.x + threadIdx.x;
    if (t < N_NODES * STATE) g_agg[t] = 0.0f;
    if (t < N_GRAPHS * STATE) g_graph[t] = 0.0f;
}

// ===========================================================================
// Register-tiled GEMM helpers.
// Block = 256 threads = 16x16; each thread computes a 4x4 tile of a
// 64-row x 64-col output block. A tile in smem [64][APITCH], W in smem [64][64].
// Per k: 4 broadcast LDS (A) + 1 LDS.128 (W) -> 16 FMAs  => FMA-bound.
// ===========================================================================

// Load a 64x64 A tile (row-major src, rowStride floats) into sA (pitch APITCH).
__device__ __forceinline__ void load_tileA(float* sA, const float* __restrict__ src,
                                           int blkRow, int rowStride, int colOff, int tid) {
#pragma unroll
    for (int p = 0; p < 4; p++) {
        int idx = p * 1024 + tid * 4;
        int row = idx >> 6, col = idx & 63;
        float4 v = make_float4(0.f, 0.f, 0.f, 0.f);
        int gr = blkRow + row;
        if (gr < N_NODES)
            v = *reinterpret_cast<const float4*>(&src[gr * rowStride + colOff + col]);
        *reinterpret_cast<float4*>(&sA[row * APITCH + col]) = v;
    }
}

// Load 64x64 weights (contiguous 4096 floats) into sW (pitch 64).
__device__ __forceinline__ void load_tileW(float* sW, const float* __restrict__ W, int tid) {
#pragma unroll
    for (int p = 0; p < 4; p++) {
        int idx = p * 1024 + tid * 4;
        *reinterpret_cast<float4*>(&sW[idx]) =
            *reinterpret_cast<const float4*>(&W[idx]);
    }
}

// acc[4][4] += A_tile @ W_tile  (K=64)
__device__ __forceinline__ void mm_tile(float acc[4][4], const float* sA, const float* sW,
                                        int r0, int c0) {
#pragma unroll 8
    for (int k = 0; k < 64; k++) {
        float4 w = *reinterpret_cast<const float4*>(&sW[k * 64 + c0]);
        float a[4];
#pragma unroll
        for (int i = 0; i < 4; i++) a[i] = sA[(r0 + i) * APITCH + k];
#pragma unroll
        for (int i = 0; i < 4; i++) {
            acc[i][0] = fmaf(a[i], w.x, acc[i][0]);
            acc[i][1] = fmaf(a[i], w.y, acc[i][1]);
            acc[i][2] = fmaf(a[i], w.z, acc[i][2]);
            acc[i][3] = fmaf(a[i], w.w, acc[i][3]);
        }
    }
}

// ---------------------------------------------------------------------------
// k_input: state = relu(x @ in_W + in_b)   [50000,128]@[128,64]
//          msg   = relu(state @ msg_W[0] + msg_b[0])       (fused)
// ---------------------------------------------------------------------------
__global__ __launch_bounds__(256) void k_input(const float* __restrict__ x,
                       const float* __restrict__ W,  const float* __restrict__ b,
                       const float* __restrict__ mW, const float* __restrict__ mb) {
    __shared__ float sA[TILE_ROWS * APITCH];
    __shared__ float sW[64 * 64];

    int tid = threadIdx.x;
    int ty = tid >> 4, tx = tid & 15;
    int r0 = ty * 4, c0 = tx * 4;
    int blkRow = blockIdx.x * TILE_ROWS;

    float acc[4][4];
#pragma unroll
    for (int i = 0; i < 4; i++)
#pragma unroll
        for (int j = 0; j < 4; j++) acc[i][j] = 0.0f;

    // Phase A: state GEMM, K=128 in two 64-chunks
#pragma unroll
    for (int chunk = 0; chunk < 2; chunk++) {
        load_tileA(sA, x, blkRow, FEAT, chunk * 64, tid);
        load_tileW(sW, W + chunk * 64 * STATE, tid);
        __syncthreads();
        mm_tile(acc, sA, sW, r0, c0);
        __syncthreads();
    }

    float4 bias = *reinterpret_cast<const float4*>(&b[c0]);
    float st[4][4];
#pragma unroll
    for (int i = 0; i < 4; i++) {
        st[i][0] = fmaxf(acc[i][0] + bias.x, 0.0f);
        st[i][1] = fmaxf(acc[i][1] + bias.y, 0.0f);
        st[i][2] = fmaxf(acc[i][2] + bias.z, 0.0f);
        st[i][3] = fmaxf(acc[i][3] + bias.w, 0.0f);
        int gr = blkRow + r0 + i;
        if (gr < N_NODES)
            *reinterpret_cast<float4*>(&g_state[gr * STATE + c0]) =
                make_float4(st[i][0], st[i][1], st[i][2], st[i][3]);
    }

    // Phase B: msg for round 0 from state tile (reuse smem)
#pragma unroll
    for (int i = 0; i < 4; i++)
        *reinterpret_cast<float4*>(&sA[(r0 + i) * APITCH + c0]) =
            make_float4(st[i][0], st[i][1], st[i][2], st[i][3]);
    load_tileW(sW, mW, tid);
    __syncthreads();

#pragma unroll
    for (int i = 0; i < 4; i++)
#pragma unroll
        for (int j = 0; j < 4; j++) acc[i][j] = 0.0f;
    mm_tile(acc, sA, sW, r0, c0);

    float4 mbias = *reinterpret_cast<const float4*>(&mb[c0]);
#pragma unroll
    for (int i = 0; i < 4; i++) {
        int gr = blkRow + r0 + i;
        if (gr < N_NODES)
            *reinterpret_cast<float4*>(&g_msg[gr * STATE + c0]) =
                make_float4(fmaxf(acc[i][0] + mbias.x, 0.0f),
                            fmaxf(acc[i][1] + mbias.y, 0.0f),
                            fmaxf(acc[i][2] + mbias.z, 0.0f),
                            fmaxf(acc[i][3] + mbias.w, 0.0f));
    }
}

// ---------------------------------------------------------------------------
// k_upd: state += relu(agg @ upd_W[r] + upd_b[r]); agg := 0
//        if HAS_MSG: msg = relu(state @ msg_W[r+1] + msg_b[r+1])   (fused)
// ---------------------------------------------------------------------------
template <int HAS_MSG>
__global__ __launch_bounds__(256) void k_upd(const float* __restrict__ W,  const float* __restrict__ b,
                     const float* __restrict__ mW, const float* __restrict__ mb) {
    __shared__ float sA[TILE_ROWS * APITCH];
    __shared__ float sW[64 * 64];

    int tid = threadIdx.x;
    int ty = tid >> 4, tx = tid & 15;
    int r0 = ty * 4, c0 = tx * 4;
    int blkRow = blockIdx.x * TILE_ROWS;

    load_tileA(sA, g_agg, blkRow, STATE, 0, tid);
    load_tileW(sW, W, tid);
    __syncthreads();

    float acc[4][4];
#pragma unroll
    for (int i = 0; i < 4; i++)
#pragma unroll
        for (int j = 0; j < 4; j++) acc[i][j] = 0.0f;
    mm_tile(acc, sA, sW, r0, c0);

    float4 bias = *reinterpret_cast<const float4*>(&b[c0]);
    float st[4][4];
    const float4 z4 = make_float4(0.f, 0.f, 0.f, 0.f);
#pragma unroll
    for (int i = 0; i < 4; i++) {
        int gr = blkRow + r0 + i;
        if (gr < N_NODES) {
            float4 old = *reinterpret_cast<const float4*>(&g_state[gr * STATE + c0]);
            st[i][0] = old.x + fmaxf(acc[i][0] + bias.x, 0.0f);
            st[i][1] = old.y + fmaxf(acc[i][1] + bias.y, 0.0f);
            st[i][2] = old.z + fmaxf(acc[i][2] + bias.z, 0.0f);
            st[i][3] = old.w + fmaxf(acc[i][3] + bias.w, 0.0f);
            *reinterpret_cast<float4*>(&g_state[gr * STATE + c0]) =
                make_float4(st[i][0], st[i][1], st[i][2], st[i][3]);
            *reinterpret_cast<float4*>(&g_agg[gr * STATE + c0]) = z4;  // re-zero
        } else {
            st[i][0] = st[i][1] = st[i][2] = st[i][3] = 0.0f;
        }
    }

    if (HAS_MSG) {
        __syncthreads();   // everyone done reading sA/sW
#pragma unroll
        for (int i = 0; i < 4; i++)
            *reinterpret_cast<float4*>(&sA[(r0 + i) * APITCH + c0]) =
                make_float4(st[i][0], st[i][1], st[i][2], st[i][3]);
        load_tileW(sW, mW, tid);
        __syncthreads();

#pragma unroll
        for (int i = 0; i < 4; i++)
#pragma unroll
            for (int j = 0; j < 4; j++) acc[i][j] = 0.0f;
        mm_tile(acc, sA, sW, r0, c0);

        float4 mbias = *reinterpret_cast<const float4*>(&mb[c0]);
#pragma unroll
        for (int i = 0; i < 4; i++) {
            int gr = blkRow + r0 + i;
            if (gr < N_NODES)
                *reinterpret_cast<float4*>(&g_msg[gr * STATE + c0]) =
                    make_float4(fmaxf(acc[i][0] + mbias.x, 0.0f),
                                fmaxf(acc[i][1] + mbias.y, 0.0f),
                                fmaxf(acc[i][2] + mbias.z, 0.0f),
                                fmaxf(acc[i][3] + mbias.w, 0.0f));
        }
    }
}

// ---------------------------------------------------------------------------
// Edge gather + scatter-add:  agg[dst] += message[src]   (indices int32)
// 16 threads/edge, float4 gather (L2-resident) + red.global.add.v4.f32
// ---------------------------------------------------------------------------
__global__ void k_edge(const int* __restrict__ ei) {
    int t = blockIdx.x * blockDim.x + threadIdx.x;
    int e = t >> 4;
    if (e >= N_EDGES) return;
    int c = (t & 15) << 2;
    int s = __ldg(&ei[e]);
    int d = __ldg(&ei[N_EDGES + e]);

    const float4 v = *reinterpret_cast<const float4*>(&g_msg[s * STATE + c]);
    float* a = &g_agg[d * STATE + c];
    asm volatile("red.global.add.v4.f32 [%0], {%1,%2,%3,%4};"
                 :: "l"(a), "f"(v.x), "f"(v.y), "f"(v.z), "f"(v.w)
                 : "memory");
}

// ---------------------------------------------------------------------------
// graph_state = segment_sum(state, batch)  -> [256, 64]
// ---------------------------------------------------------------------------
__global__ void k_pool(const int* __restrict__ batch) {
    int t = blockIdx.x * blockDim.x + threadIdx.x;
    int row = t >> 4;
    if (row >= N_NODES) return;
    int c = (t & 15) << 2;
    int g = __ldg(&batch[row]);

    const float4 v = *reinterpret_cast<const float4*>(&g_state[row * STATE + c]);
    float* a = &g_graph[g * STATE + c];
    asm volatile("red.global.add.v4.f32 [%0], {%1,%2,%3,%4};"
                 :: "l"(a), "f"(v.x), "f"(v.y), "f"(v.z), "f"(v.w)
                 : "memory");
}

// ---------------------------------------------------------------------------
// mean = gs @ mean_W + mean_b ; std = exp(0.5*clip(gs @ lv_W + lv_b, -20, 2))
// ---------------------------------------------------------------------------
__global__ void k_head(const float* __restrict__ meanW, const float* __restrict__ meanB,
                       const float* __restrict__ lvW,   const float* __restrict__ lvB,
                       float* __restrict__ out) {
    __shared__ float s[STATE];
    int g = blockIdx.x;
    int m = threadIdx.x;
    s[m]      = g_graph[g * STATE + m];
    s[m + 32] = g_graph[g * STATE + m + 32];
    __syncthreads();

    float accM = meanB[m];
    float accL = lvB[m];
#pragma unroll
    for (int k = 0; k < STATE; k++) {
        float sv = s[k];
        accM = fmaf(sv, meanW[k * M_OUT + m], accM);
        accL = fmaf(sv, lvW[k * M_OUT + m], accL);
    }
    out[g * M_OUT + m] = accM;
    float lv = fminf(fmaxf(accL, -20.0f), 2.0f);
    out[N_GRAPHS * M_OUT + g * M_OUT + m] = expf(0.5f * lv);
}

// ---------------------------------------------------------------------------
extern "C" void kernel_launch(void* const* d_in, const int* in_sizes, int n_in,
                              void* d_out, int out_size) {
    const float* x     = (const float*)d_in[0];
    const int*   ei    = (const int*)d_in[1];
    const int*   batch = (const int*)d_in[2];
    const float* in_W  = (const float*)d_in[3];
    const float* in_b  = (const float*)d_in[4];
    const float* msg_W = (const float*)d_in[5];    // [4,64,64]
    const float* msg_b = (const float*)d_in[6];    // [4,64]
    const float* upd_W = (const float*)d_in[7];
    const float* upd_b = (const float*)d_in[8];
    const float* meanW = (const float*)d_in[9];
    const float* meanB = (const float*)d_in[10];
    const float* lvW   = (const float*)d_in[11];
    const float* lvB   = (const float*)d_in[12];
    float* out = (float*)d_out;

    const int zeroBlocks = (N_NODES * STATE + 255) / 256;
    const int edgeBlocks = (N_EDGES * 16 + 255) / 256;
    const int poolBlocks = (N_NODES * 16 + 255) / 256;

    k_zero<<<zeroBlocks, 256>>>();
    k_input<<<ROW_BLOCKS, 256>>>(x, in_W, in_b, msg_W, msg_b);  // state + msg[0]

    for (int r = 0; r < ROUNDS; r++) {
        k_edge<<<edgeBlocks, 256>>>(ei);
        const float* uW = upd_W + r * STATE * STATE;
        const float* ub = upd_b + r * STATE;
        if (r < ROUNDS - 1) {
            k_upd<1><<<ROW_BLOCKS, 256>>>(uW, ub,
                                          msg_W + (r + 1) * STATE * STATE,
                                          msg_b + (r + 1) * STATE);
        } else {
            k_upd<0><<<ROW_BLOCKS, 256>>>(uW, ub, nullptr, nullptr);
        }
    }

    k_pool<<<poolBlocks, 256>>>(batch);
    k_head<<<N_GRAPHS, M_OUT>>>(meanW, meanB, lvW, lvB, out);
}

// round 10
// speedup vs baseline: 2.3412x; 1.0449x over previous
#include <cuda_runtime.h>
#include <math.h>

#define N_NODES  50000
#define N_EDGES  800000
#define N_GRAPHS 256
#define FEAT     128
#define STATE    64
#define ROUNDS   4
#define M_OUT    32

#define TILE_ROWS 64
#define APITCH    68          // padded smem pitch (floats) -> no bank conflicts
#define ROW_BLOCKS ((N_NODES + TILE_ROWS - 1) / TILE_ROWS)   // 782

// Scratch (allocation-free rule: __device__ globals)
__device__ float g_state[N_NODES * STATE];   // 12.8 MB
__device__ float g_msg[N_NODES * STATE];     // 12.8 MB
__device__ float g_agg[N_NODES * STATE];     // 12.8 MB
__device__ float g_graph[N_GRAPHS * STATE];  // 64 KB
// CSR-by-dst scratch (built once per launch, reused all 4 rounds)
__device__ int   g_cnt[N_NODES];
__device__ int   g_rowptr[N_NODES + 1];
__device__ int   g_cursor[N_NODES];
__device__ int   g_esrc[N_EDGES];

// ---------------------------------------------------------------------------
// Zero degree counters + graph accumulator (agg no longer needs zeroing:
// the CSR gather overwrites every row).
// ---------------------------------------------------------------------------
__global__ void k_zero() {
    int t = blockIdx.x * blockDim.x + threadIdx.x;
    if (t < N_NODES) g_cnt[t] = 0;
    if (t < N_GRAPHS * STATE) g_graph[t] = 0.0f;
}

// ---------------------------------------------------------------------------
// CSR build: histogram of dst, exclusive scan, stable-ish scatter of src ids
// ---------------------------------------------------------------------------
__global__ void k_hist(const int* __restrict__ ei) {
    int t = blockIdx.x * blockDim.x + threadIdx.x;
    if (t < N_EDGES) atomicAdd(&g_cnt[__ldg(&ei[N_EDGES + t])], 1);
}

// single block, 1024 threads: exclusive scan of g_cnt -> g_rowptr, g_cursor
__global__ __launch_bounds__(1024) void k_scan() {
    __shared__ int ps[1024];
    const int CH = (N_NODES + 1023) / 1024;   // 49
    int t = threadIdx.x;
    int base = t * CH;

    int sum = 0;
    for (int i = 0; i < CH; i++) {
        int idx = base + i;
        if (idx < N_NODES) sum += g_cnt[idx];
    }
    ps[t] = sum;
    __syncthreads();
    // Hillis-Steele inclusive scan
    for (int off = 1; off < 1024; off <<= 1) {
        int v = (t >= off) ? ps[t - off] : 0;
        __syncthreads();
        ps[t] += v;
        __syncthreads();
    }
    int run = (t == 0) ? 0 : ps[t - 1];
    for (int i = 0; i < CH; i++) {
        int idx = base + i;
        if (idx < N_NODES) {
            int c = g_cnt[idx];
            g_rowptr[idx] = run;
            g_cursor[idx] = run;
            run += c;
        }
    }
    if (t == 1023) g_rowptr[N_NODES] = run;   // = N_EDGES
}

__global__ void k_scatter(const int* __restrict__ ei) {
    int t = blockIdx.x * blockDim.x + threadIdx.x;
    if (t >= N_EDGES) return;
    int d = __ldg(&ei[N_EDGES + t]);
    int pos = atomicAdd(&g_cursor[d], 1);
    g_esrc[pos] = __ldg(&ei[t]);
}

// ===========================================================================
// Register-tiled GEMM helpers (unchanged from R8 winner).
// ===========================================================================
__device__ __forceinline__ void load_tileA(float* sA, const float* __restrict__ src,
                                           int blkRow, int rowStride, int colOff, int tid) {
#pragma unroll
    for (int p = 0; p < 4; p++) {
        int idx = p * 1024 + tid * 4;
        int row = idx >> 6, col = idx & 63;
        float4 v = make_float4(0.f, 0.f, 0.f, 0.f);
        int gr = blkRow + row;
        if (gr < N_NODES)
            v = *reinterpret_cast<const float4*>(&src[gr * rowStride + colOff + col]);
        *reinterpret_cast<float4*>(&sA[row * APITCH + col]) = v;
    }
}

__device__ __forceinline__ void load_tileW(float* sW, const float* __restrict__ W, int tid) {
#pragma unroll
    for (int p = 0; p < 4; p++) {
        int idx = p * 1024 + tid * 4;
        *reinterpret_cast<float4*>(&sW[idx]) =
            *reinterpret_cast<const float4*>(&W[idx]);
    }
}

__device__ __forceinline__ void mm_tile(float acc[4][4], const float* sA, const float* sW,
                                        int r0, int c0) {
#pragma unroll 8
    for (int k = 0; k < 64; k++) {
        float4 w = *reinterpret_cast<const float4*>(&sW[k * 64 + c0]);
        float a[4];
#pragma unroll
        for (int i = 0; i < 4; i++) a[i] = sA[(r0 + i) * APITCH + k];
#pragma unroll
        for (int i = 0; i < 4; i++) {
            acc[i][0] = fmaf(a[i], w.x, acc[i][0]);
            acc[i][1] = fmaf(a[i], w.y, acc[i][1]);
            acc[i][2] = fmaf(a[i], w.z, acc[i][2]);
            acc[i][3] = fmaf(a[i], w.w, acc[i][3]);
        }
    }
}

// ---------------------------------------------------------------------------
// k_input: state = relu(x @ in_W + in_b); msg = relu(state @ msg_W[0] + b0)
// ---------------------------------------------------------------------------
__global__ __launch_bounds__(256) void k_input(const float* __restrict__ x,
                       const float* __restrict__ W,  const float* __restrict__ b,
                       const float* __restrict__ mW, const float* __restrict__ mb) {
    __shared__ float sA[TILE_ROWS * APITCH];
    __shared__ float sW[64 * 64];

    int tid = threadIdx.x;
    int ty = tid >> 4, tx = tid & 15;
    int r0 = ty * 4, c0 = tx * 4;
    int blkRow = blockIdx.x * TILE_ROWS;

    float acc[4][4];
#pragma unroll
    for (int i = 0; i < 4; i++)
#pragma unroll
        for (int j = 0; j < 4; j++) acc[i][j] = 0.0f;

#pragma unroll
    for (int chunk = 0; chunk < 2; chunk++) {
        load_tileA(sA, x, blkRow, FEAT, chunk * 64, tid);
        load_tileW(sW, W + chunk * 64 * STATE, tid);
        __syncthreads();
        mm_tile(acc, sA, sW, r0, c0);
        __syncthreads();
    }

    float4 bias = *reinterpret_cast<const float4*>(&b[c0]);
    float st[4][4];
#pragma unroll
    for (int i = 0; i < 4; i++) {
        st[i][0] = fmaxf(acc[i][0] + bias.x, 0.0f);
        st[i][1] = fmaxf(acc[i][1] + bias.y, 0.0f);
        st[i][2] = fmaxf(acc[i][2] + bias.z, 0.0f);
        st[i][3] = fmaxf(acc[i][3] + bias.w, 0.0f);
        int gr = blkRow + r0 + i;
        if (gr < N_NODES)
            *reinterpret_cast<float4*>(&g_state[gr * STATE + c0]) =
                make_float4(st[i][0], st[i][1], st[i][2], st[i][3]);
    }

    // msg[0] from the state tile (reuse smem)
#pragma unroll
    for (int i = 0; i < 4; i++)
        *reinterpret_cast<float4*>(&sA[(r0 + i) * APITCH + c0]) =
            make_float4(st[i][0], st[i][1], st[i][2], st[i][3]);
    load_tileW(sW, mW, tid);
    __syncthreads();

#pragma unroll
    for (int i = 0; i < 4; i++)
#pragma unroll
        for (int j = 0; j < 4; j++) acc[i][j] = 0.0f;
    mm_tile(acc, sA, sW, r0, c0);

    float4 mbias = *reinterpret_cast<const float4*>(&mb[c0]);
#pragma unroll
    for (int i = 0; i < 4; i++) {
        int gr = blkRow + r0 + i;
        if (gr < N_NODES)
            *reinterpret_cast<float4*>(&g_msg[gr * STATE + c0]) =
                make_float4(fmaxf(acc[i][0] + mbias.x, 0.0f),
                            fmaxf(acc[i][1] + mbias.y, 0.0f),
                            fmaxf(acc[i][2] + mbias.z, 0.0f),
                            fmaxf(acc[i][3] + mbias.w, 0.0f));
    }
}

// ---------------------------------------------------------------------------
// CSR gather: agg[n] = sum_{e in csr(n)} msg[esrc[e]]   (atomic-free)
// 16 threads per node, float4 lanes; 2-edge unroll for load MLP.
// ---------------------------------------------------------------------------
__global__ __launch_bounds__(256) void k_gather() {
    int t = blockIdx.x * blockDim.x + threadIdx.x;
    int node = t >> 4;
    if (node >= N_NODES) return;
    int c = (t & 15) << 2;

    int beg = __ldg(&g_rowptr[node]);
    int end = __ldg(&g_rowptr[node + 1]);

    float4 acc = make_float4(0.f, 0.f, 0.f, 0.f);
    int e = beg;
    for (; e + 1 < end; e += 2) {
        int s0 = __ldg(&g_esrc[e]);
        int s1 = __ldg(&g_esrc[e + 1]);
        float4 v0 = *reinterpret_cast<const float4*>(&g_msg[s0 * STATE + c]);
        float4 v1 = *reinterpret_cast<const float4*>(&g_msg[s1 * STATE + c]);
        acc.x += v0.x + v1.x;
        acc.y += v0.y + v1.y;
        acc.z += v0.z + v1.z;
        acc.w += v0.w + v1.w;
    }
    if (e < end) {
        int s0 = __ldg(&g_esrc[e]);
        float4 v0 = *reinterpret_cast<const float4*>(&g_msg[s0 * STATE + c]);
        acc.x += v0.x; acc.y += v0.y; acc.z += v0.z; acc.w += v0.w;
    }
    *reinterpret_cast<float4*>(&g_agg[node * STATE + c]) = acc;
}

// ---------------------------------------------------------------------------
// k_upd: state += relu(agg @ upd_W[r] + upd_b[r])
//        if HAS_MSG: msg = relu(state @ msg_W[r+1] + msg_b[r+1])
// (no agg re-zero needed anymore)
// ---------------------------------------------------------------------------
template <int HAS_MSG>
__global__ __launch_bounds__(256) void k_upd(const float* __restrict__ W,  const float* __restrict__ b,
                     const float* __restrict__ mW, const float* __restrict__ mb) {
    __shared__ float sA[TILE_ROWS * APITCH];
    __shared__ float sW[64 * 64];

    int tid = threadIdx.x;
    int ty = tid >> 4, tx = tid & 15;
    int r0 = ty * 4, c0 = tx * 4;
    int blkRow = blockIdx.x * TILE_ROWS;

    load_tileA(sA, g_agg, blkRow, STATE, 0, tid);
    load_tileW(sW, W, tid);
    __syncthreads();

    float acc[4][4];
#pragma unroll
    for (int i = 0; i < 4; i++)
#pragma unroll
        for (int j = 0; j < 4; j++) acc[i][j] = 0.0f;
    mm_tile(acc, sA, sW, r0, c0);

    float4 bias = *reinterpret_cast<const float4*>(&b[c0]);
    float st[4][4];
#pragma unroll
    for (int i = 0; i < 4; i++) {
        int gr = blkRow + r0 + i;
        if (gr < N_NODES) {
            float4 old = *reinterpret_cast<const float4*>(&g_state[gr * STATE + c0]);
            st[i][0] = old.x + fmaxf(acc[i][0] + bias.x, 0.0f);
            st[i][1] = old.y + fmaxf(acc[i][1] + bias.y, 0.0f);
            st[i][2] = old.z + fmaxf(acc[i][2] + bias.z, 0.0f);
            st[i][3] = old.w + fmaxf(acc[i][3] + bias.w, 0.0f);
            *reinterpret_cast<float4*>(&g_state[gr * STATE + c0]) =
                make_float4(st[i][0], st[i][1], st[i][2], st[i][3]);
        } else {
            st[i][0] = st[i][1] = st[i][2] = st[i][3] = 0.0f;
        }
    }

    if (HAS_MSG) {
        __syncthreads();
#pragma unroll
        for (int i = 0; i < 4; i++)
            *reinterpret_cast<float4*>(&sA[(r0 + i) * APITCH + c0]) =
                make_float4(st[i][0], st[i][1], st[i][2], st[i][3]);
        load_tileW(sW, mW, tid);
        __syncthreads();

#pragma unroll
        for (int i = 0; i < 4; i++)
#pragma unroll
            for (int j = 0; j < 4; j++) acc[i][j] = 0.0f;
        mm_tile(acc, sA, sW, r0, c0);

        float4 mbias = *reinterpret_cast<const float4*>(&mb[c0]);
#pragma unroll
        for (int i = 0; i < 4; i++) {
            int gr = blkRow + r0 + i;
            if (gr < N_NODES)
                *reinterpret_cast<float4*>(&g_msg[gr * STATE + c0]) =
                    make_float4(fmaxf(acc[i][0] + mbias.x, 0.0f),
                                fmaxf(acc[i][1] + mbias.y, 0.0f),
                                fmaxf(acc[i][2] + mbias.z, 0.0f),
                                fmaxf(acc[i][3] + mbias.w, 0.0f));
        }
    }
}

// ---------------------------------------------------------------------------
// graph_state = segment_sum(state, batch)  -> [256, 64]
// ---------------------------------------------------------------------------
__global__ void k_pool(const int* __restrict__ batch) {
    int t = blockIdx.x * blockDim.x + threadIdx.x;
    int row = t >> 4;
    if (row >= N_NODES) return;
    int c = (t & 15) << 2;
    int g = __ldg(&batch[row]);

    const float4 v = *reinterpret_cast<const float4*>(&g_state[row * STATE + c]);
    float* a = &g_graph[g * STATE + c];
    asm volatile("red.global.add.v4.f32 [%0], {%1,%2,%3,%4};"
                 :: "l"(a), "f"(v.x), "f"(v.y), "f"(v.z), "f"(v.w)
                 : "memory");
}

// ---------------------------------------------------------------------------
// mean = gs @ mean_W + mean_b ; std = exp(0.5*clip(gs @ lv_W + lv_b, -20, 2))
// ---------------------------------------------------------------------------
__global__ void k_head(const float* __restrict__ meanW, const float* __restrict__ meanB,
                       const float* __restrict__ lvW,   const float* __restrict__ lvB,
                       float* __restrict__ out) {
    __shared__ float s[STATE];
    int g = blockIdx.x;
    int m = threadIdx.x;
    s[m]      = g_graph[g * STATE + m];
    s[m + 32] = g_graph[g * STATE + m + 32];
    __syncthreads();

    float accM = meanB[m];
    float accL = lvB[m];
#pragma unroll
    for (int k = 0; k < STATE; k++) {
        float sv = s[k];
        accM = fmaf(sv, meanW[k * M_OUT + m], accM);
        accL = fmaf(sv, lvW[k * M_OUT + m], accL);
    }
    out[g * M_OUT + m] = accM;
    float lv = fminf(fmaxf(accL, -20.0f), 2.0f);
    out[N_GRAPHS * M_OUT + g * M_OUT + m] = expf(0.5f * lv);
}

// ---------------------------------------------------------------------------
extern "C" void kernel_launch(void* const* d_in, const int* in_sizes, int n_in,
                              void* d_out, int out_size) {
    const float* x     = (const float*)d_in[0];
    const int*   ei    = (const int*)d_in[1];
    const int*   batch = (const int*)d_in[2];
    const float* in_W  = (const float*)d_in[3];
    const float* in_b  = (const float*)d_in[4];
    const float* msg_W = (const float*)d_in[5];    // [4,64,64]
    const float* msg_b = (const float*)d_in[6];    // [4,64]
    const float* upd_W = (const float*)d_in[7];
    const float* upd_b = (const float*)d_in[8];
    const float* meanW = (const float*)d_in[9];
    const float* meanB = (const float*)d_in[10];
    const float* lvW   = (const float*)d_in[11];
    const float* lvB   = (const float*)d_in[12];
    float* out = (float*)d_out;

    const int zeroBlocks   = (N_NODES + 255) / 256;
    const int edgeBlocks   = (N_EDGES + 255) / 256;
    const int gatherBlocks = (N_NODES * 16 + 255) / 256;
    const int poolBlocks   = (N_NODES * 16 + 255) / 256;

    // CSR build (once per launch; reused by all 4 rounds)
    k_zero<<<zeroBlocks, 256>>>();
    k_hist<<<edgeBlocks, 256>>>(ei);
    k_scan<<<1, 1024>>>();
    k_scatter<<<edgeBlocks, 256>>>(ei);

    k_input<<<ROW_BLOCKS, 256>>>(x, in_W, in_b, msg_W, msg_b);  // state + msg[0]

    for (int r = 0; r < ROUNDS; r++) {
        k_gather<<<gatherBlocks, 256>>>();
        const float* uW = upd_W + r * STATE * STATE;
        const float* ub = upd_b + r * STATE;
        if (r < ROUNDS - 1) {
            k_upd<1><<<ROW_BLOCKS, 256>>>(uW, ub,
                                          msg_W + (r + 1) * STATE * STATE,
                                          msg_b + (r + 1) * STATE);
        } else {
            k_upd<0><<<ROW_BLOCKS, 256>>>(uW, ub, nullptr, nullptr);
        }
    }

    k_pool<<<poolBlocks, 256>>>(batch);
    k_head<<<N_GRAPHS, M_OUT>>>(meanW, meanB, lvW, lvB, out);
}